// round 10
// baseline (speedup 1.0000x reference)
#include <cuda_runtime.h>
#include <cstdint>

#define NN 50000
#define NE 800000
#define HID 64

// ---------------- scratch (device globals; no allocations allowed) ----------
__device__ __align__(16) float g_q[NN * HID];
__device__ __align__(16) float g_k[NN * HID];
__device__ __align__(16) float g_v[NN * HID];
__device__ __align__(16) float g_skip[NN * HID];
__device__ __align__(16) float g_agg[NN * HID];     // h between layers
__device__ __align__(16) float g_logit[NE];         // spill for deg>32 nodes only
__device__ __align__(16) float g_eLs[NE * 5];       // log1p(edge_attr), sorted by dst
__device__ __align__(16) int   g_srcs[NE];          // src node, sorted by dst
__device__ __align__(16) int   g_rowptr[NN + 1];
__device__ __align__(16) int   g_cnt[NN];

#define NEG_INF __int_as_float(0xff800000)

__device__ __forceinline__ unsigned long long pack2(float lo, float hi) {
    unsigned long long r;
    asm("mov.b64 %0, {%1, %2};" : "=l"(r) : "f"(lo), "f"(hi));
    return r;
}
__device__ __forceinline__ void ffma2(unsigned long long& d,
                                      unsigned long long a, unsigned long long b) {
    asm("fma.rn.f32x2 %0, %1, %2, %0;" : "+l"(d) : "l"(a), "l"(b));
}

// ---------------- CSR build: zero, histogram, scan, scatter ----------------
__global__ void kzero() {
    int i = blockIdx.x * blockDim.x + threadIdx.x;
    if (i < NN) g_cnt[i] = 0;
}

__global__ void khist(const int* __restrict__ ei) {
    int e = blockIdx.x * blockDim.x + threadIdx.x;
    if (e < NE) atomicAdd(&g_cnt[ei[NE + e]], 1);
}

// single-block exclusive scan over g_cnt -> g_rowptr; re-zeros g_cnt
__global__ __launch_bounds__(1024) void kscan() {
    const int t = threadIdx.x;
    const int lane = t & 31, wid = t >> 5;
    __shared__ int warp_sums[32];
    __shared__ int carry_s;
    if (t == 0) carry_s = 0;
    __syncthreads();
    for (int base = 0; base < NN; base += 1024) {
        int i = base + t;
        int v = (i < NN) ? g_cnt[i] : 0;
        if (i < NN) g_cnt[i] = 0;
        int x = v;
        #pragma unroll
        for (int o = 1; o < 32; o <<= 1) {
            int y = __shfl_up_sync(0xffffffffu, x, o);
            if (lane >= o) x += y;
        }
        if (lane == 31) warp_sums[wid] = x;
        __syncthreads();
        if (wid == 0) {
            int ws = warp_sums[lane];
            #pragma unroll
            for (int o = 1; o < 32; o <<= 1) {
                int y = __shfl_up_sync(0xffffffffu, ws, o);
                if (lane >= o) ws += y;
            }
            warp_sums[lane] = ws;
        }
        __syncthreads();
        int incl = x + (wid > 0 ? warp_sums[wid - 1] : 0);
        if (i < NN) g_rowptr[i] = incl - v + carry_s;
        __syncthreads();
        if (t == 1023) carry_s += incl;
        __syncthreads();
    }
    if (t == 0) g_rowptr[NN] = carry_s;
}

__global__ void kscatter(const int* __restrict__ ei, const float* __restrict__ ea) {
    int e = blockIdx.x * blockDim.x + threadIdx.x;
    if (e >= NE) return;
    int sn = ei[e], dn = ei[NE + e];
    int pos = g_rowptr[dn] + atomicAdd(&g_cnt[dn], 1);
    g_srcs[pos] = sn;
    #pragma unroll
    for (int d = 0; d < 5; d++)
        g_eLs[pos * 5 + d] = log1pf(ea[e * 5 + d]);
}

// ---------------- K1: per-layer node GEMM (q,k,v,skip fused, f32x2) --------
__global__ __launch_bounds__(256) void k1_node(
    const float* __restrict__ xin, int kin, int mode,
    const float* __restrict__ wq, const float* __restrict__ bq,
    const float* __restrict__ wk, const float* __restrict__ bk,
    const float* __restrict__ wv, const float* __restrict__ bv,
    const float* __restrict__ wsk, const float* __restrict__ bsk)
{
    extern __shared__ float smbuf[];
    float* hd = smbuf;                        // [kin][64] float2 (h duplicated)
    float* Ws = smbuf + 2 * 64 * kin;         // [kin][256]
    float* Bs = Ws + kin * 256;               // [256]

    const int t = threadIdx.x;
    const int base = blockIdx.x * 64;

    {
        const float* wptr[4] = {wq, wk, wv, wsk};
        for (int idx = t; idx < kin * 256; idx += 256) {
            int kk = idx >> 8, cc = idx & 255;
            Ws[idx] = wptr[cc >> 6][kk * 64 + (cc & 63)];
        }
        const float* bptr[4] = {bq, bk, bv, bsk};
        Bs[t] = bptr[t >> 6][t & 63];
    }

    if (mode == 0) {
        for (int idx = t; idx < 64 * kin; idx += 256) {
            int r = idx & 63, c = idx >> 6;          // c < kin
            int n = base + r;
            float v = (n < NN) ? log1pf(xin[n * 10 + c]) : 0.0f;
            hd[(c * 64 + r) * 2]     = v;
            hd[(c * 64 + r) * 2 + 1] = v;
        }
    } else {
        for (int idx = t; idx < 64 * 64; idx += 256) {
            int r = idx & 63, c = idx >> 6;
            int n = base + r;
            float v = (n < NN) ? g_agg[(size_t)n * 64 + c] : 0.0f;
            hd[(c * 64 + r) * 2]     = v;
            hd[(c * 64 + r) * 2 + 1] = v;
        }
    }
    __syncthreads();

    const int tc = t & 31;   // col pairs: 2*tc + 64*jj
    const int tr = t >> 5;   // nodes: tr*8 + i

    unsigned long long acc[8][4];
    #pragma unroll
    for (int jj = 0; jj < 4; jj++) {
        float2 b2 = *(const float2*)(Bs + jj * 64 + 2 * tc);
        unsigned long long bb = pack2(b2.x, b2.y);
        #pragma unroll
        for (int i = 0; i < 8; i++) acc[i][jj] = bb;
    }

    for (int kk = 0; kk < kin; kk++) {
        unsigned long long hv[8], wv2[4];
        #pragma unroll
        for (int i = 0; i < 8; i++)
            hv[i] = *(const unsigned long long*)(hd + (kk * 64 + tr * 8 + i) * 2);
        #pragma unroll
        for (int jj = 0; jj < 4; jj++)
            wv2[jj] = *(const unsigned long long*)(Ws + kk * 256 + jj * 64 + 2 * tc);
        #pragma unroll
        for (int i = 0; i < 8; i++)
            #pragma unroll
            for (int jj = 0; jj < 4; jj++)
                ffma2(acc[i][jj], hv[i], wv2[jj]);
    }

    float* mats[4] = {g_q, g_k, g_v, g_skip};
    #pragma unroll
    for (int i = 0; i < 8; i++) {
        int n = base + tr * 8 + i;
        if (n >= NN) continue;
        #pragma unroll
        for (int jj = 0; jj < 4; jj++)
            *(unsigned long long*)(mats[jj] + (size_t)n * 64 + 2 * tc) = acc[i][jj];
    }
}

// ---------------- kedge: warp-per-node, two independent-iteration loops ----
// 4 groups of 8 lanes; group g handles local edges g, g+4, g+8, ...
// Loop1: logits -> per-lane register slot (lane i holds logit of local edge i,
//        i<32; rare deg>32 tail spills to g_logit). Iterations independent.
// Butterfly max (5 shuffles), then Loop2: exp+accumulate with known m
// (iterations independent, accumulator-carried only). Group merge = plain adds.
__global__ __launch_bounds__(256) void kedge(const float* __restrict__ we)
{
    int n = (blockIdx.x * 256 + threadIdx.x) >> 5;
    int lane = threadIdx.x & 31;
    int g  = lane >> 3;
    int li = lane & 7;
    unsigned gmask = 0xFFu << (g * 8);
    if (n >= NN) return;

    const int start = g_rowptr[n];
    const int deg   = g_rowptr[n + 1] - start;
    const size_t nb = (size_t)n * 64 + li * 8;

    if (deg == 0) {                 // degree 0: h = skip
        if (g == 0) {
            float4 s0 = *(const float4*)(g_skip + nb);
            float4 s1 = *(const float4*)(g_skip + nb + 4);
            *(float4*)(g_agg + nb)     = s0;
            *(float4*)(g_agg + nb + 4) = s1;
        }
        return;
    }

    float4 q0 = *(const float4*)(g_q + nb);
    float4 q1 = *(const float4*)(g_q + nb + 4);

    // r[d] = we[d,:] . q   (group-local reduction; all groups same value)
    float r[5];
    #pragma unroll
    for (int d = 0; d < 5; d++) {
        float4 w0 = __ldg((const float4*)(we + d * 64 + li * 8));
        float4 w1 = __ldg((const float4*)(we + d * 64 + li * 8 + 4));
        float pr = w0.x*q0.x + w0.y*q0.y + w0.z*q0.z + w0.w*q0.w
                 + w1.x*q1.x + w1.y*q1.y + w1.z*q1.z + w1.w*q1.w;
        pr += __shfl_xor_sync(gmask, pr, 1);
        pr += __shfl_xor_sync(gmask, pr, 2);
        pr += __shfl_xor_sync(gmask, pr, 4);
        r[d] = pr;
    }

    const int nIter = (deg + 3) >> 2;
    const int srcLane = (lane & 3) * 8;   // group (lane&3)'s lane 0

    // ---- loop 1: logits (independent iterations) ----
    float mylg = NEG_INF;      // lane i: logit of local edge i (i < 32)
    float mreg = NEG_INF;
    #pragma unroll 2
    for (int j = 0; j < nIter; j++) {
        int local = 4 * j + g;
        bool act = (local < deg);
        int p0 = start + (act ? local : 0);
        int sn = __ldg(g_srcs + p0);
        const float* kp = g_k + (size_t)sn * 64 + li * 8;
        float4 k0 = *(const float4*)(kp);
        float4 k1 = *(const float4*)(kp + 4);
        float e0 = __ldg(g_eLs + p0 * 5 + 0), e1 = __ldg(g_eLs + p0 * 5 + 1),
              e2 = __ldg(g_eLs + p0 * 5 + 2), e3 = __ldg(g_eLs + p0 * 5 + 3),
              e4 = __ldg(g_eLs + p0 * 5 + 4);

        float dot = q0.x*k0.x + q0.y*k0.y + q0.z*k0.z + q0.w*k0.w
                  + q1.x*k1.x + q1.y*k1.y + q1.z*k1.z + q1.w*k1.w;
        dot += __shfl_xor_sync(gmask, dot, 1);
        dot += __shfl_xor_sync(gmask, dot, 2);
        dot += __shfl_xor_sync(gmask, dot, 4);
        float lg = act ? (dot + r[0]*e0 + r[1]*e1 + r[2]*e2 + r[3]*e3 + r[4]*e4) * 0.125f
                       : NEG_INF;
        mreg = fmaxf(mreg, lg);

        // distribute: lane i (i>>2 == j) takes group (i&3)'s logit (edge 4j+(i&3))
        float dv = __shfl_sync(0xffffffffu, lg, srcLane);
        if ((lane >> 2) == j) mylg = dv;
        if (local >= 32 && act && li == 0) g_logit[p0] = lg;   // rare spill
    }

    // ---- warp max ----
    float m = mreg;
    #pragma unroll
    for (int o = 16; o; o >>= 1) m = fmaxf(m, __shfl_xor_sync(0xffffffffu, m, o));

    // ---- loop 2: exp + accumulate (independent iterations) ----
    float s = 0.0f;
    float a0x=0, a0y=0, a0z=0, a0w=0, a1x=0, a1y=0, a1z=0, a1w=0;
    float t0=0, t1=0, t2=0, t3=0, t4=0;
    #pragma unroll 2
    for (int j = 0; j < nIter; j++) {
        int local = 4 * j + g;
        bool act = (local < deg);
        int p0 = start + (act ? local : 0);
        int sn = __ldg(g_srcs + p0);
        const float* vp = g_v + (size_t)sn * 64 + li * 8;
        float4 v0 = *(const float4*)(vp);
        float4 v1 = *(const float4*)(vp + 4);
        float e0 = __ldg(g_eLs + p0 * 5 + 0), e1 = __ldg(g_eLs + p0 * 5 + 1),
              e2 = __ldg(g_eLs + p0 * 5 + 2), e3 = __ldg(g_eLs + p0 * 5 + 3),
              e4 = __ldg(g_eLs + p0 * 5 + 4);

        float lg;
        if (j < 8) {                    // warp-uniform branch
            lg = __shfl_sync(0xffffffffu, mylg, local & 31);
        } else {
            lg = act ? g_logit[p0] : NEG_INF;
        }
        float p = __expf(lg - m);       // inactive lanes: exp(-inf - m) = 0
        s += p;
        a0x += p*v0.x; a0y += p*v0.y; a0z += p*v0.z; a0w += p*v0.w;
        a1x += p*v1.x; a1y += p*v1.y; a1z += p*v1.z; a1w += p*v1.w;
        t0 += p*e0; t1 += p*e1; t2 += p*e2; t3 += p*e3; t4 += p*e4;
    }

    // ---- merge 4 group states (plain sums; lanes at xor 8,16 share dims) ----
    #pragma unroll
    for (int off = 8; off <= 16; off <<= 1) {
        s   += __shfl_xor_sync(0xffffffffu, s,   off);
        a0x += __shfl_xor_sync(0xffffffffu, a0x, off);
        a0y += __shfl_xor_sync(0xffffffffu, a0y, off);
        a0z += __shfl_xor_sync(0xffffffffu, a0z, off);
        a0w += __shfl_xor_sync(0xffffffffu, a0w, off);
        a1x += __shfl_xor_sync(0xffffffffu, a1x, off);
        a1y += __shfl_xor_sync(0xffffffffu, a1y, off);
        a1z += __shfl_xor_sync(0xffffffffu, a1z, off);
        a1w += __shfl_xor_sync(0xffffffffu, a1w, off);
        t0  += __shfl_xor_sync(0xffffffffu, t0,  off);
        t1  += __shfl_xor_sync(0xffffffffu, t1,  off);
        t2  += __shfl_xor_sync(0xffffffffu, t2,  off);
        t3  += __shfl_xor_sync(0xffffffffu, t3,  off);
        t4  += __shfl_xor_sync(0xffffffffu, t4,  off);
    }

    if (g == 0) {
        float inv = 1.0f / s;           // s >= 1 (max term contributes 1)
        float4 s0 = *(const float4*)(g_skip + nb);
        float4 s1 = *(const float4*)(g_skip + nb + 4);
        float hv[8] = {a0x, a0y, a0z, a0w, a1x, a1y, a1z, a1w};
        float tt[5] = {t0, t1, t2, t3, t4};
        #pragma unroll
        for (int d = 0; d < 5; d++) {
            float4 w0 = __ldg((const float4*)(we + d * 64 + li * 8));
            float4 w1 = __ldg((const float4*)(we + d * 64 + li * 8 + 4));
            hv[0] += tt[d]*w0.x; hv[1] += tt[d]*w0.y;
            hv[2] += tt[d]*w0.z; hv[3] += tt[d]*w0.w;
            hv[4] += tt[d]*w1.x; hv[5] += tt[d]*w1.y;
            hv[6] += tt[d]*w1.z; hv[7] += tt[d]*w1.w;
        }
        float4 h0, h1;
        h0.x = hv[0]*inv + s0.x; h0.y = hv[1]*inv + s0.y;
        h0.z = hv[2]*inv + s0.z; h0.w = hv[3]*inv + s0.w;
        h1.x = hv[4]*inv + s1.x; h1.y = hv[5]*inv + s1.y;
        h1.z = hv[6]*inv + s1.z; h1.w = hv[7]*inv + s1.w;
        *(float4*)(g_agg + nb)     = h0;
        *(float4*)(g_agg + nb + 4) = h1;
    }
}

// ---------------- final: out = h @ lin_w + lin_b ---------------------------
__global__ __launch_bounds__(256) void kfinal(const float* __restrict__ lw,
                                              const float* __restrict__ lb,
                                              float* __restrict__ out)
{
    int n = (blockIdx.x * blockDim.x + threadIdx.x) >> 5;
    int lane = threadIdx.x & 31;
    if (n >= NN) return;
    float2 h  = *(const float2*)(g_agg + (size_t)n * 64 + lane * 2);
    float2 wv = *(const float2*)(lw + lane * 2);
    float part = h.x * wv.x + h.y * wv.y;
    #pragma unroll
    for (int o = 16; o; o >>= 1) part += __shfl_xor_sync(0xffffffffu, part, o);
    if (lane == 0) out[n] = part + lb[0];
}

// ---------------- driver ----------------------------------------------------
extern "C" void kernel_launch(void* const* d_in, const int* in_sizes, int n_in,
                              void* d_out, int out_size)
{
    const float* x   = (const float*)d_in[0];
    const int*   ei  = (const int*)d_in[1];       // int32 (jax x64 disabled)
    const float* ea  = (const float*)d_in[2];
    const float* w1q = (const float*)d_in[3];  const float* b1q = (const float*)d_in[4];
    const float* w1k = (const float*)d_in[5];  const float* b1k = (const float*)d_in[6];
    const float* w1v = (const float*)d_in[7];  const float* b1v = (const float*)d_in[8];
    const float* w1e = (const float*)d_in[9];
    const float* w1s = (const float*)d_in[10]; const float* b1s = (const float*)d_in[11];
    const float* wq  = (const float*)d_in[12]; const float* bq  = (const float*)d_in[13];
    const float* wk  = (const float*)d_in[14]; const float* bk  = (const float*)d_in[15];
    const float* wv  = (const float*)d_in[16]; const float* bv  = (const float*)d_in[17];
    const float* we  = (const float*)d_in[18];
    const float* ws  = (const float*)d_in[19]; const float* bs  = (const float*)d_in[20];
    const float* lw  = (const float*)d_in[21]; const float* lb  = (const float*)d_in[22];
    float* out = (float*)d_out;

    cudaFuncSetAttribute(k1_node, cudaFuncAttributeMaxDynamicSharedMemorySize, 104 * 1024);

    const int nb1 = (NN + 63) / 64;
    const size_t smem10 = (size_t)(2 * 64 * 10 + 10 * 256 + 256) * sizeof(float);
    const size_t smem64 = (size_t)(2 * 64 * 64 + 64 * 256 + 256) * sizeof(float);
    const int nbN = (NN + 255) / 256;
    const int nbE = (NE + 255) / 256;
    const int nbW = (NN * 32 + 255) / 256;   // warp-per-node grids

    // build CSR (edge_index constant; rebuilt identically each replay)
    kzero<<<nbN, 256>>>();
    khist<<<nbE, 256>>>(ei);
    kscan<<<1, 1024>>>();
    kscatter<<<nbE, 256>>>(ei, ea);

    // layer 0 (10 -> 64)
    k1_node<<<nb1, 256, smem10>>>(x, 10, 0, w1q, b1q, w1k, b1k, w1v, b1v, w1s, b1s);
    kedge<<<nbW, 256>>>(w1e);

    // layers 1..5 (64 -> 64)
    for (int l = 0; l < 5; l++) {
        k1_node<<<nb1, 256, smem64>>>(nullptr, 64, 1,
                                      wq + l * 4096, bq + l * 64,
                                      wk + l * 4096, bk + l * 64,
                                      wv + l * 4096, bv + l * 64,
                                      ws + l * 4096, bs + l * 64);
        kedge<<<nbW, 256>>>(we + l * 320);
    }

    kfinal<<<nbW, 256>>>(lw, lb, out);
}

// round 12
// speedup vs baseline: 1.0281x; 1.0281x over previous
#include <cuda_runtime.h>
#include <cstdint>

#define NN 50000
#define NE 800000
#define HID 64

// ---------------- scratch (device globals; no allocations allowed) ----------
__device__ __align__(16) float g_q[NN * HID];
__device__ __align__(16) float g_k[NN * HID];
__device__ __align__(16) float g_v[NN * HID];
__device__ __align__(16) float g_skip[NN * HID];
__device__ __align__(16) float g_agg[NN * HID];     // h between layers
__device__ __align__(16) float g_eLs[NE * 5];       // log1p(edge_attr), sorted by dst
__device__ __align__(16) int   g_srcs[NE];          // src node, sorted by dst
__device__ __align__(16) int   g_rowptr[NN + 1];
__device__ __align__(16) int   g_cnt[NN];

#define NEG_INF __int_as_float(0xff800000)

__device__ __forceinline__ unsigned long long pack2(float lo, float hi) {
    unsigned long long r;
    asm("mov.b64 %0, {%1, %2};" : "=l"(r) : "f"(lo), "f"(hi));
    return r;
}
__device__ __forceinline__ void ffma2(unsigned long long& d,
                                      unsigned long long a, unsigned long long b) {
    asm("fma.rn.f32x2 %0, %1, %2, %0;" : "+l"(d) : "l"(a), "l"(b));
}

// ---------------- CSR build: zero, histogram, scan, scatter ----------------
__global__ void kzero() {
    int i = blockIdx.x * blockDim.x + threadIdx.x;
    if (i < NN) g_cnt[i] = 0;
}

__global__ void khist(const int* __restrict__ ei) {
    int e = blockIdx.x * blockDim.x + threadIdx.x;
    if (e < NE) atomicAdd(&g_cnt[ei[NE + e]], 1);
}

// single-block exclusive scan over g_cnt -> g_rowptr; re-zeros g_cnt
__global__ __launch_bounds__(1024) void kscan() {
    const int t = threadIdx.x;
    const int lane = t & 31, wid = t >> 5;
    __shared__ int warp_sums[32];
    __shared__ int carry_s;
    if (t == 0) carry_s = 0;
    __syncthreads();
    for (int base = 0; base < NN; base += 1024) {
        int i = base + t;
        int v = (i < NN) ? g_cnt[i] : 0;
        if (i < NN) g_cnt[i] = 0;
        int x = v;
        #pragma unroll
        for (int o = 1; o < 32; o <<= 1) {
            int y = __shfl_up_sync(0xffffffffu, x, o);
            if (lane >= o) x += y;
        }
        if (lane == 31) warp_sums[wid] = x;
        __syncthreads();
        if (wid == 0) {
            int ws = warp_sums[lane];
            #pragma unroll
            for (int o = 1; o < 32; o <<= 1) {
                int y = __shfl_up_sync(0xffffffffu, ws, o);
                if (lane >= o) ws += y;
            }
            warp_sums[lane] = ws;
        }
        __syncthreads();
        int incl = x + (wid > 0 ? warp_sums[wid - 1] : 0);
        if (i < NN) g_rowptr[i] = incl - v + carry_s;
        __syncthreads();
        if (t == 1023) carry_s += incl;
        __syncthreads();
    }
    if (t == 0) g_rowptr[NN] = carry_s;
}

__global__ void kscatter(const int* __restrict__ ei, const float* __restrict__ ea) {
    int e = blockIdx.x * blockDim.x + threadIdx.x;
    if (e >= NE) return;
    int sn = ei[e], dn = ei[NE + e];
    int pos = g_rowptr[dn] + atomicAdd(&g_cnt[dn], 1);
    g_srcs[pos] = sn;
    #pragma unroll
    for (int d = 0; d < 5; d++)
        g_eLs[pos * 5 + d] = log1pf(ea[e * 5 + d]);
}

// ---------------- K1: per-layer node GEMM (q,k,v,skip fused, f32x2) --------
__global__ __launch_bounds__(256) void k1_node(
    const float* __restrict__ xin, int kin, int mode,
    const float* __restrict__ wq, const float* __restrict__ bq,
    const float* __restrict__ wk, const float* __restrict__ bk,
    const float* __restrict__ wv, const float* __restrict__ bv,
    const float* __restrict__ wsk, const float* __restrict__ bsk)
{
    extern __shared__ float smbuf[];
    float* hd = smbuf;                        // [kin][64] float2 (h duplicated)
    float* Ws = smbuf + 2 * 64 * kin;         // [kin][256]
    float* Bs = Ws + kin * 256;               // [256]

    const int t = threadIdx.x;
    const int base = blockIdx.x * 64;

    {
        const float* wptr[4] = {wq, wk, wv, wsk};
        for (int idx = t; idx < kin * 256; idx += 256) {
            int kk = idx >> 8, cc = idx & 255;
            Ws[idx] = wptr[cc >> 6][kk * 64 + (cc & 63)];
        }
        const float* bptr[4] = {bq, bk, bv, bsk};
        Bs[t] = bptr[t >> 6][t & 63];
    }

    if (mode == 0) {
        for (int idx = t; idx < 64 * kin; idx += 256) {
            int r = idx & 63, c = idx >> 6;          // c < kin
            int n = base + r;
            float v = (n < NN) ? log1pf(xin[n * 10 + c]) : 0.0f;
            hd[(c * 64 + r) * 2]     = v;
            hd[(c * 64 + r) * 2 + 1] = v;
        }
    } else {
        for (int idx = t; idx < 64 * 64; idx += 256) {
            int r = idx & 63, c = idx >> 6;
            int n = base + r;
            float v = (n < NN) ? g_agg[(size_t)n * 64 + c] : 0.0f;
            hd[(c * 64 + r) * 2]     = v;
            hd[(c * 64 + r) * 2 + 1] = v;
        }
    }
    __syncthreads();

    const int tc = t & 31;   // col pairs: 2*tc + 64*jj
    const int tr = t >> 5;   // nodes: tr*8 + i

    unsigned long long acc[8][4];
    #pragma unroll
    for (int jj = 0; jj < 4; jj++) {
        float2 b2 = *(const float2*)(Bs + jj * 64 + 2 * tc);
        unsigned long long bb = pack2(b2.x, b2.y);
        #pragma unroll
        for (int i = 0; i < 8; i++) acc[i][jj] = bb;
    }

    for (int kk = 0; kk < kin; kk++) {
        unsigned long long hv[8], wv2[4];
        #pragma unroll
        for (int i = 0; i < 8; i++)
            hv[i] = *(const unsigned long long*)(hd + (kk * 64 + tr * 8 + i) * 2);
        #pragma unroll
        for (int jj = 0; jj < 4; jj++)
            wv2[jj] = *(const unsigned long long*)(Ws + kk * 256 + jj * 64 + 2 * tc);
        #pragma unroll
        for (int i = 0; i < 8; i++)
            #pragma unroll
            for (int jj = 0; jj < 4; jj++)
                ffma2(acc[i][jj], hv[i], wv2[jj]);
    }

    float* mats[4] = {g_q, g_k, g_v, g_skip};
    #pragma unroll
    for (int i = 0; i < 8; i++) {
        int n = base + tr * 8 + i;
        if (n >= NN) continue;
        #pragma unroll
        for (int jj = 0; jj < 4; jj++)
            *(unsigned long long*)(mats[jj] + (size_t)n * 64 + 2 * tc) = acc[i][jj];
    }
}

// ---------------- kedge: warp-per-node, 8 edges in flight ------------------
// 4 groups of 8 lanes; group g handles edges (start+g) with stride 4, but
// processes TWO edges (p0, p0+4) per iteration -> 8 edges in flight per warp
// and half the online-rescale chain length.
__global__ __launch_bounds__(256) void kedge(const float* __restrict__ we)
{
    int n = (blockIdx.x * 256 + threadIdx.x) >> 5;
    int lane = threadIdx.x & 31;
    int g  = lane >> 3;
    int li = lane & 7;
    unsigned gmask = 0xFFu << (g * 8);
    if (n >= NN) return;

    const int start = g_rowptr[n];
    const int end   = g_rowptr[n + 1];
    const size_t nb = (size_t)n * 64 + li * 8;

    if (start == end) {                 // degree 0: h = skip
        if (g == 0) {
            float4 s0 = *(const float4*)(g_skip + nb);
            float4 s1 = *(const float4*)(g_skip + nb + 4);
            *(float4*)(g_agg + nb)     = s0;
            *(float4*)(g_agg + nb + 4) = s1;
        }
        return;
    }

    float4 q0 = *(const float4*)(g_q + nb);
    float4 q1 = *(const float4*)(g_q + nb + 4);

    // r[d] = we[d,:] . q   (group-local reduction; all groups same value)
    float r[5];
    #pragma unroll
    for (int d = 0; d < 5; d++) {
        float4 w0 = __ldg((const float4*)(we + d * 64 + li * 8));
        float4 w1 = __ldg((const float4*)(we + d * 64 + li * 8 + 4));
        float pr = w0.x*q0.x + w0.y*q0.y + w0.z*q0.z + w0.w*q0.w
                 + w1.x*q1.x + w1.y*q1.y + w1.z*q1.z + w1.w*q1.w;
        pr += __shfl_xor_sync(gmask, pr, 1);
        pr += __shfl_xor_sync(gmask, pr, 2);
        pr += __shfl_xor_sync(gmask, pr, 4);
        r[d] = pr;
    }

    float m = NEG_INF, s = 0.0f;
    float a0x=0, a0y=0, a0z=0, a0w=0, a1x=0, a1y=0, a1z=0, a1w=0;
    float t0=0, t1=0, t2=0, t3=0, t4=0;

    for (int pAi = start + g; pAi < end; pAi += 8) {
        // edge A (always valid: pAi < end), edge B (may be out of range)
        int pBi = pAi + 4;
        bool actB = (pBi < end);
        int pBc = actB ? pBi : pAi;

        int snA = __ldg(g_srcs + pAi);
        int snB = __ldg(g_srcs + pBc);
        const float* kpA = g_k + (size_t)snA * 64 + li * 8;
        const float* kpB = g_k + (size_t)snB * 64 + li * 8;
        const float* vpA = g_v + (size_t)snA * 64 + li * 8;
        const float* vpB = g_v + (size_t)snB * 64 + li * 8;
        float4 kA0 = *(const float4*)(kpA);
        float4 kA1 = *(const float4*)(kpA + 4);
        float4 kB0 = *(const float4*)(kpB);
        float4 kB1 = *(const float4*)(kpB + 4);
        float4 vA0 = *(const float4*)(vpA);
        float4 vA1 = *(const float4*)(vpA + 4);
        float4 vB0 = *(const float4*)(vpB);
        float4 vB1 = *(const float4*)(vpB + 4);
        float eA0 = __ldg(g_eLs + pAi * 5 + 0), eA1 = __ldg(g_eLs + pAi * 5 + 1),
              eA2 = __ldg(g_eLs + pAi * 5 + 2), eA3 = __ldg(g_eLs + pAi * 5 + 3),
              eA4 = __ldg(g_eLs + pAi * 5 + 4);
        float eB0 = __ldg(g_eLs + pBc * 5 + 0), eB1 = __ldg(g_eLs + pBc * 5 + 1),
              eB2 = __ldg(g_eLs + pBc * 5 + 2), eB3 = __ldg(g_eLs + pBc * 5 + 3),
              eB4 = __ldg(g_eLs + pBc * 5 + 4);

        float dotA = q0.x*kA0.x + q0.y*kA0.y + q0.z*kA0.z + q0.w*kA0.w
                   + q1.x*kA1.x + q1.y*kA1.y + q1.z*kA1.z + q1.w*kA1.w;
        float dotB = q0.x*kB0.x + q0.y*kB0.y + q0.z*kB0.z + q0.w*kB0.w
                   + q1.x*kB1.x + q1.y*kB1.y + q1.z*kB1.z + q1.w*kB1.w;
        dotA += __shfl_xor_sync(gmask, dotA, 1);
        dotB += __shfl_xor_sync(gmask, dotB, 1);
        dotA += __shfl_xor_sync(gmask, dotA, 2);
        dotB += __shfl_xor_sync(gmask, dotB, 2);
        dotA += __shfl_xor_sync(gmask, dotA, 4);
        dotB += __shfl_xor_sync(gmask, dotB, 4);

        float lgA = (dotA + r[0]*eA0 + r[1]*eA1 + r[2]*eA2 + r[3]*eA3 + r[4]*eA4) * 0.125f;
        float lgB = actB
                  ? (dotB + r[0]*eB0 + r[1]*eB1 + r[2]*eB2 + r[3]*eB3 + r[4]*eB4) * 0.125f
                  : NEG_INF;

        float mx = fmaxf(lgA, lgB);
        if (mx > m) {                  // group-uniform branch
            float sc = __expf(m - mx); // first iter: exp(-inf)=0, accs are 0
            s *= sc;
            a0x*=sc; a0y*=sc; a0z*=sc; a0w*=sc;
            a1x*=sc; a1y*=sc; a1z*=sc; a1w*=sc;
            t0*=sc; t1*=sc; t2*=sc; t3*=sc; t4*=sc;
            m = mx;
        }
        float pA = __expf(lgA - m);
        float pB = __expf(lgB - m);    // 0 when inactive (lgB = -inf)
        s += pA + pB;
        a0x += pA*vA0.x + pB*vB0.x; a0y += pA*vA0.y + pB*vB0.y;
        a0z += pA*vA0.z + pB*vB0.z; a0w += pA*vA0.w + pB*vB0.w;
        a1x += pA*vA1.x + pB*vB1.x; a1y += pA*vA1.y + pB*vB1.y;
        a1z += pA*vA1.z + pB*vB1.z; a1w += pA*vA1.w + pB*vB1.w;
        t0 += pA*eA0 + pB*eB0; t1 += pA*eA1 + pB*eB1; t2 += pA*eA2 + pB*eB2;
        t3 += pA*eA3 + pB*eB3; t4 += pA*eA4 + pB*eB4;
    }

    // merge the 4 group states (lanes at xor 8, 16 hold the same dims)
    #pragma unroll
    for (int off = 8; off <= 16; off <<= 1) {
        float mo  = __shfl_xor_sync(0xffffffffu, m,  off);
        float so  = __shfl_xor_sync(0xffffffffu, s,  off);
        float b0x = __shfl_xor_sync(0xffffffffu, a0x, off);
        float b0y = __shfl_xor_sync(0xffffffffu, a0y, off);
        float b0z = __shfl_xor_sync(0xffffffffu, a0z, off);
        float b0w = __shfl_xor_sync(0xffffffffu, a0w, off);
        float b1x = __shfl_xor_sync(0xffffffffu, a1x, off);
        float b1y = __shfl_xor_sync(0xffffffffu, a1y, off);
        float b1z = __shfl_xor_sync(0xffffffffu, a1z, off);
        float b1w = __shfl_xor_sync(0xffffffffu, a1w, off);
        float u0  = __shfl_xor_sync(0xffffffffu, t0, off);
        float u1  = __shfl_xor_sync(0xffffffffu, t1, off);
        float u2  = __shfl_xor_sync(0xffffffffu, t2, off);
        float u3  = __shfl_xor_sync(0xffffffffu, t3, off);
        float u4  = __shfl_xor_sync(0xffffffffu, t4, off);

        float mn = fmaxf(m, mo);
        float sa = (m  > NEG_INF) ? __expf(m  - mn) : 0.0f;  // guard empty groups
        float sb = (mo > NEG_INF) ? __expf(mo - mn) : 0.0f;
        m = mn;
        s = s*sa + so*sb;
        a0x = a0x*sa + b0x*sb; a0y = a0y*sa + b0y*sb;
        a0z = a0z*sa + b0z*sb; a0w = a0w*sa + b0w*sb;
        a1x = a1x*sa + b1x*sb; a1y = a1y*sa + b1y*sb;
        a1z = a1z*sa + b1z*sb; a1w = a1w*sa + b1w*sb;
        t0 = t0*sa + u0*sb; t1 = t1*sa + u1*sb; t2 = t2*sa + u2*sb;
        t3 = t3*sa + u3*sb; t4 = t4*sa + u4*sb;
    }

    if (g == 0) {
        float inv = 1.0f / s;    // s >= 1 after merge
        float4 s0 = *(const float4*)(g_skip + nb);
        float4 s1 = *(const float4*)(g_skip + nb + 4);
        float hv[8] = {a0x, a0y, a0z, a0w, a1x, a1y, a1z, a1w};
        float tt[5] = {t0, t1, t2, t3, t4};
        #pragma unroll
        for (int d = 0; d < 5; d++) {
            float4 w0 = __ldg((const float4*)(we + d * 64 + li * 8));
            float4 w1 = __ldg((const float4*)(we + d * 64 + li * 8 + 4));
            hv[0] += tt[d]*w0.x; hv[1] += tt[d]*w0.y;
            hv[2] += tt[d]*w0.z; hv[3] += tt[d]*w0.w;
            hv[4] += tt[d]*w1.x; hv[5] += tt[d]*w1.y;
            hv[6] += tt[d]*w1.z; hv[7] += tt[d]*w1.w;
        }
        float4 h0, h1;
        h0.x = hv[0]*inv + s0.x; h0.y = hv[1]*inv + s0.y;
        h0.z = hv[2]*inv + s0.z; h0.w = hv[3]*inv + s0.w;
        h1.x = hv[4]*inv + s1.x; h1.y = hv[5]*inv + s1.y;
        h1.z = hv[6]*inv + s1.z; h1.w = hv[7]*inv + s1.w;
        *(float4*)(g_agg + nb)     = h0;
        *(float4*)(g_agg + nb + 4) = h1;
    }
}

// ---------------- final: out = h @ lin_w + lin_b ---------------------------
__global__ __launch_bounds__(256) void kfinal(const float* __restrict__ lw,
                                              const float* __restrict__ lb,
                                              float* __restrict__ out)
{
    int n = (blockIdx.x * blockDim.x + threadIdx.x) >> 5;
    int lane = threadIdx.x & 31;
    if (n >= NN) return;
    float2 h  = *(const float2*)(g_agg + (size_t)n * 64 + lane * 2);
    float2 wv = *(const float2*)(lw + lane * 2);
    float part = h.x * wv.x + h.y * wv.y;
    #pragma unroll
    for (int o = 16; o; o >>= 1) part += __shfl_xor_sync(0xffffffffu, part, o);
    if (lane == 0) out[n] = part + lb[0];
}

// ---------------- driver ----------------------------------------------------
extern "C" void kernel_launch(void* const* d_in, const int* in_sizes, int n_in,
                              void* d_out, int out_size)
{
    const float* x   = (const float*)d_in[0];
    const int*   ei  = (const int*)d_in[1];       // int32 (jax x64 disabled)
    const float* ea  = (const float*)d_in[2];
    const float* w1q = (const float*)d_in[3];  const float* b1q = (const float*)d_in[4];
    const float* w1k = (const float*)d_in[5];  const float* b1k = (const float*)d_in[6];
    const float* w1v = (const float*)d_in[7];  const float* b1v = (const float*)d_in[8];
    const float* w1e = (const float*)d_in[9];
    const float* w1s = (const float*)d_in[10]; const float* b1s = (const float*)d_in[11];
    const float* wq  = (const float*)d_in[12]; const float* bq  = (const float*)d_in[13];
    const float* wk  = (const float*)d_in[14]; const float* bk  = (const float*)d_in[15];
    const float* wv  = (const float*)d_in[16]; const float* bv  = (const float*)d_in[17];
    const float* we  = (const float*)d_in[18];
    const float* ws  = (const float*)d_in[19]; const float* bs  = (const float*)d_in[20];
    const float* lw  = (const float*)d_in[21]; const float* lb  = (const float*)d_in[22];
    float* out = (float*)d_out;

    cudaFuncSetAttribute(k1_node, cudaFuncAttributeMaxDynamicSharedMemorySize, 104 * 1024);

    const int nb1 = (NN + 63) / 64;
    const size_t smem10 = (size_t)(2 * 64 * 10 + 10 * 256 + 256) * sizeof(float);
    const size_t smem64 = (size_t)(2 * 64 * 64 + 64 * 256 + 256) * sizeof(float);
    const int nbN = (NN + 255) / 256;
    const int nbE = (NE + 255) / 256;
    const int nbW = (NN * 32 + 255) / 256;   // warp-per-node grids

    // build CSR (edge_index constant; rebuilt identically each replay)
    kzero<<<nbN, 256>>>();
    khist<<<nbE, 256>>>(ei);
    kscan<<<1, 1024>>>();
    kscatter<<<nbE, 256>>>(ei, ea);

    // layer 0 (10 -> 64)
    k1_node<<<nb1, 256, smem10>>>(x, 10, 0, w1q, b1q, w1k, b1k, w1v, b1v, w1s, b1s);
    kedge<<<nbW, 256>>>(w1e);

    // layers 1..5 (64 -> 64)
    for (int l = 0; l < 5; l++) {
        k1_node<<<nb1, 256, smem64>>>(nullptr, 64, 1,
                                      wq + l * 4096, bq + l * 64,
                                      wk + l * 4096, bk + l * 64,
                                      wv + l * 4096, bv + l * 64,
                                      ws + l * 4096, bs + l * 64);
        kedge<<<nbW, 256>>>(we + l * 320);
    }

    kfinal<<<nbW, 256>>>(lw, lb, out);
}

// round 13
// speedup vs baseline: 1.1345x; 1.1035x over previous
#include <cuda_runtime.h>
#include <cstdint>

#define NN 50000
#define NE 800000
#define HID 64

// ---------------- scratch (device globals; no allocations allowed) ----------
__device__ __align__(16) float g_q[NN * HID];
__device__ __align__(16) float g_k[NN * HID];
__device__ __align__(16) float g_v[NN * HID];
__device__ __align__(16) float g_skip[NN * HID];
__device__ __align__(16) float g_agg[NN * HID];     // h between layers
__device__ __align__(16) float g_eLs[NE * 5];       // log1p(edge_attr), sorted by dst
__device__ __align__(16) int   g_srcs[NE];          // src node, sorted by dst
__device__ __align__(16) int   g_rowptr[NN + 1];
__device__ __align__(16) int   g_cnt[NN];

#define NEG_INF __int_as_float(0xff800000)

__device__ __forceinline__ unsigned long long pack2(float lo, float hi) {
    unsigned long long r;
    asm("mov.b64 %0, {%1, %2};" : "=l"(r) : "f"(lo), "f"(hi));
    return r;
}
__device__ __forceinline__ void ffma2(unsigned long long& d,
                                      unsigned long long a, unsigned long long b) {
    asm("fma.rn.f32x2 %0, %1, %2, %0;" : "+l"(d) : "l"(a), "l"(b));
}

// ---------------- CSR build: zero, histogram, scan, scatter ----------------
__global__ void kzero() {
    int i = blockIdx.x * blockDim.x + threadIdx.x;
    if (i < NN) g_cnt[i] = 0;
}

__global__ void khist(const int* __restrict__ ei) {
    int e = blockIdx.x * blockDim.x + threadIdx.x;
    if (e < NE) atomicAdd(&g_cnt[ei[NE + e]], 1);
}

// single-block exclusive scan over g_cnt -> g_rowptr; re-zeros g_cnt
__global__ __launch_bounds__(1024) void kscan() {
    const int t = threadIdx.x;
    const int lane = t & 31, wid = t >> 5;
    __shared__ int warp_sums[32];
    __shared__ int carry_s;
    if (t == 0) carry_s = 0;
    __syncthreads();
    for (int base = 0; base < NN; base += 1024) {
        int i = base + t;
        int v = (i < NN) ? g_cnt[i] : 0;
        if (i < NN) g_cnt[i] = 0;
        int x = v;
        #pragma unroll
        for (int o = 1; o < 32; o <<= 1) {
            int y = __shfl_up_sync(0xffffffffu, x, o);
            if (lane >= o) x += y;
        }
        if (lane == 31) warp_sums[wid] = x;
        __syncthreads();
        if (wid == 0) {
            int ws = warp_sums[lane];
            #pragma unroll
            for (int o = 1; o < 32; o <<= 1) {
                int y = __shfl_up_sync(0xffffffffu, ws, o);
                if (lane >= o) ws += y;
            }
            warp_sums[lane] = ws;
        }
        __syncthreads();
        int incl = x + (wid > 0 ? warp_sums[wid - 1] : 0);
        if (i < NN) g_rowptr[i] = incl - v + carry_s;
        __syncthreads();
        if (t == 1023) carry_s += incl;
        __syncthreads();
    }
    if (t == 0) g_rowptr[NN] = carry_s;
}

__global__ void kscatter(const int* __restrict__ ei, const float* __restrict__ ea) {
    int e = blockIdx.x * blockDim.x + threadIdx.x;
    if (e >= NE) return;
    int sn = ei[e], dn = ei[NE + e];
    int pos = g_rowptr[dn] + atomicAdd(&g_cnt[dn], 1);
    g_srcs[pos] = sn;
    #pragma unroll
    for (int d = 0; d < 5; d++)
        g_eLs[pos * 5 + d] = log1pf(ea[e * 5 + d]);
}

// ---------------- K1: per-layer node GEMM (q,k,v,skip fused, f32x2) --------
// h tile stored once [kin][64]; (v,v) pairs packed in registers.
// smem = 4*(64*kin + kin*256 + 256) bytes -> 81KB at kin=64 => 2 blocks/SM.
__global__ __launch_bounds__(256) void k1_node(
    const float* __restrict__ xin, int kin, int mode,
    const float* __restrict__ wq, const float* __restrict__ bq,
    const float* __restrict__ wk, const float* __restrict__ bk,
    const float* __restrict__ wv, const float* __restrict__ bv,
    const float* __restrict__ wsk, const float* __restrict__ bsk)
{
    extern __shared__ float smbuf[];
    float* hs = smbuf;                        // [kin][64]  (hs[c*64+r])
    float* Ws = smbuf + 64 * kin;             // [kin][256]
    float* Bs = Ws + kin * 256;               // [256]

    const int t = threadIdx.x;
    const int base = blockIdx.x * 64;

    {
        const float* wptr[4] = {wq, wk, wv, wsk};
        for (int idx = t; idx < kin * 256; idx += 256) {
            int kk = idx >> 8, cc = idx & 255;
            Ws[idx] = wptr[cc >> 6][kk * 64 + (cc & 63)];
        }
        const float* bptr[4] = {bq, bk, bv, bsk};
        Bs[t] = bptr[t >> 6][t & 63];
    }

    if (mode == 0) {
        // kin=10: scalar, c fastest for coalesced gmem reads
        for (int idx = t; idx < 64 * kin; idx += 256) {
            int r = idx / kin, c = idx - r * kin;
            int n = base + r;
            hs[c * 64 + r] = (n < NN) ? log1pf(xin[n * 10 + c]) : 0.0f;
        }
    } else {
        // coalesced float4 gmem reads; transposed scalar smem writes
        // thread t: row r = t>>2, quad q = (t&3) + 4*i
        int r = t >> 2;
        int n = base + r;
        #pragma unroll
        for (int i = 0; i < 4; i++) {
            int q = (t & 3) + 4 * i;            // 0..15
            float4 va = (n < NN)
                ? *(const float4*)(g_agg + (size_t)n * 64 + q * 4)
                : make_float4(0.f, 0.f, 0.f, 0.f);
            hs[(q * 4 + 0) * 64 + r] = va.x;
            hs[(q * 4 + 1) * 64 + r] = va.y;
            hs[(q * 4 + 2) * 64 + r] = va.z;
            hs[(q * 4 + 3) * 64 + r] = va.w;
        }
    }
    __syncthreads();

    const int tc = t & 31;   // col pairs: 2*tc + 64*jj
    const int tr = t >> 5;   // nodes: tr*8 + i

    unsigned long long acc[8][4];
    #pragma unroll
    for (int jj = 0; jj < 4; jj++) {
        float2 b2 = *(const float2*)(Bs + jj * 64 + 2 * tc);
        unsigned long long bb = pack2(b2.x, b2.y);
        #pragma unroll
        for (int i = 0; i < 8; i++) acc[i][jj] = bb;
    }

    for (int kk = 0; kk < kin; kk++) {
        float4 ha = *(const float4*)(hs + kk * 64 + tr * 8);      // broadcast
        float4 hb = *(const float4*)(hs + kk * 64 + tr * 8 + 4);  // broadcast
        unsigned long long hv[8];
        hv[0] = pack2(ha.x, ha.x); hv[1] = pack2(ha.y, ha.y);
        hv[2] = pack2(ha.z, ha.z); hv[3] = pack2(ha.w, ha.w);
        hv[4] = pack2(hb.x, hb.x); hv[5] = pack2(hb.y, hb.y);
        hv[6] = pack2(hb.z, hb.z); hv[7] = pack2(hb.w, hb.w);
        unsigned long long wv2[4];
        #pragma unroll
        for (int jj = 0; jj < 4; jj++)
            wv2[jj] = *(const unsigned long long*)(Ws + kk * 256 + jj * 64 + 2 * tc);
        #pragma unroll
        for (int i = 0; i < 8; i++)
            #pragma unroll
            for (int jj = 0; jj < 4; jj++)
                ffma2(acc[i][jj], hv[i], wv2[jj]);
    }

    float* mats[4] = {g_q, g_k, g_v, g_skip};
    #pragma unroll
    for (int i = 0; i < 8; i++) {
        int n = base + tr * 8 + i;
        if (n >= NN) continue;
        #pragma unroll
        for (int jj = 0; jj < 4; jj++)
            *(unsigned long long*)(mats[jj] + (size_t)n * 64 + 2 * tc) = acc[i][jj];
    }
}

// ---------------- kedge: warp-per-node, 4 edges in flight, branchless ------
// 4 groups of 8 lanes; group g handles edges start+g, start+g+4, ...
// Online softmax with BRANCHLESS rescale: straight-line loop body so ptxas
// can software-pipeline the next iteration's gathers over this one's tail.
__global__ __launch_bounds__(256) void kedge(const float* __restrict__ we)
{
    int n = (blockIdx.x * 256 + threadIdx.x) >> 5;
    int lane = threadIdx.x & 31;
    int g  = lane >> 3;
    int li = lane & 7;
    unsigned gmask = 0xFFu << (g * 8);
    if (n >= NN) return;

    const int start = g_rowptr[n];
    const int end   = g_rowptr[n + 1];
    const size_t nb = (size_t)n * 64 + li * 8;

    if (start == end) {                 // degree 0: h = skip
        if (g == 0) {
            float4 s0 = *(const float4*)(g_skip + nb);
            float4 s1 = *(const float4*)(g_skip + nb + 4);
            *(float4*)(g_agg + nb)     = s0;
            *(float4*)(g_agg + nb + 4) = s1;
        }
        return;
    }

    float4 q0 = *(const float4*)(g_q + nb);
    float4 q1 = *(const float4*)(g_q + nb + 4);

    // r[d] = we[d,:] . q   (group-local reduction; all groups same value)
    float r[5];
    #pragma unroll
    for (int d = 0; d < 5; d++) {
        float4 w0 = __ldg((const float4*)(we + d * 64 + li * 8));
        float4 w1 = __ldg((const float4*)(we + d * 64 + li * 8 + 4));
        float pr = w0.x*q0.x + w0.y*q0.y + w0.z*q0.z + w0.w*q0.w
                 + w1.x*q1.x + w1.y*q1.y + w1.z*q1.z + w1.w*q1.w;
        pr += __shfl_xor_sync(gmask, pr, 1);
        pr += __shfl_xor_sync(gmask, pr, 2);
        pr += __shfl_xor_sync(gmask, pr, 4);
        r[d] = pr;
    }

    float m = NEG_INF, s = 0.0f;
    float a0x=0, a0y=0, a0z=0, a0w=0, a1x=0, a1y=0, a1z=0, a1w=0;
    float t0=0, t1=0, t2=0, t3=0, t4=0;

    for (int p0 = start + g; p0 < end; p0 += 4) {
        int sn = __ldg(g_srcs + p0);
        const float* kp = g_k + (size_t)sn * 64 + li * 8;
        const float* vp = g_v + (size_t)sn * 64 + li * 8;
        float4 k0 = *(const float4*)(kp);
        float4 k1 = *(const float4*)(kp + 4);
        float4 v0 = *(const float4*)(vp);
        float4 v1 = *(const float4*)(vp + 4);
        float e0 = __ldg(g_eLs + p0 * 5 + 0), e1 = __ldg(g_eLs + p0 * 5 + 1),
              e2 = __ldg(g_eLs + p0 * 5 + 2), e3 = __ldg(g_eLs + p0 * 5 + 3),
              e4 = __ldg(g_eLs + p0 * 5 + 4);

        float dot = q0.x*k0.x + q0.y*k0.y + q0.z*k0.z + q0.w*k0.w
                  + q1.x*k1.x + q1.y*k1.y + q1.z*k1.z + q1.w*k1.w;
        dot += __shfl_xor_sync(gmask, dot, 1);
        dot += __shfl_xor_sync(gmask, dot, 2);
        dot += __shfl_xor_sync(gmask, dot, 4);
        float lg = (dot + r[0]*e0 + r[1]*e1 + r[2]*e2 + r[3]*e3 + r[4]*e4) * 0.125f;

        // branchless online rescale: first iter sc = exp(-inf) = 0
        float mn = fmaxf(m, lg);
        float sc = __expf(m - mn);
        float p  = __expf(lg - mn);
        m = mn;
        s   = s  *sc + p;
        a0x = a0x*sc + p*v0.x; a0y = a0y*sc + p*v0.y;
        a0z = a0z*sc + p*v0.z; a0w = a0w*sc + p*v0.w;
        a1x = a1x*sc + p*v1.x; a1y = a1y*sc + p*v1.y;
        a1z = a1z*sc + p*v1.z; a1w = a1w*sc + p*v1.w;
        t0  = t0 *sc + p*e0;   t1  = t1 *sc + p*e1;
        t2  = t2 *sc + p*e2;   t3  = t3 *sc + p*e3;
        t4  = t4 *sc + p*e4;
    }

    // merge the 4 group states (lanes at xor 8, 16 hold the same dims)
    #pragma unroll
    for (int off = 8; off <= 16; off <<= 1) {
        float mo  = __shfl_xor_sync(0xffffffffu, m,  off);
        float so  = __shfl_xor_sync(0xffffffffu, s,  off);
        float b0x = __shfl_xor_sync(0xffffffffu, a0x, off);
        float b0y = __shfl_xor_sync(0xffffffffu, a0y, off);
        float b0z = __shfl_xor_sync(0xffffffffu, a0z, off);
        float b0w = __shfl_xor_sync(0xffffffffu, a0w, off);
        float b1x = __shfl_xor_sync(0xffffffffu, a1x, off);
        float b1y = __shfl_xor_sync(0xffffffffu, a1y, off);
        float b1z = __shfl_xor_sync(0xffffffffu, a1z, off);
        float b1w = __shfl_xor_sync(0xffffffffu, a1w, off);
        float u0  = __shfl_xor_sync(0xffffffffu, t0, off);
        float u1  = __shfl_xor_sync(0xffffffffu, t1, off);
        float u2  = __shfl_xor_sync(0xffffffffu, t2, off);
        float u3  = __shfl_xor_sync(0xffffffffu, t3, off);
        float u4  = __shfl_xor_sync(0xffffffffu, t4, off);

        float mn = fmaxf(m, mo);
        float sa = (m  > NEG_INF) ? __expf(m  - mn) : 0.0f;  // guard empty groups
        float sb = (mo > NEG_INF) ? __expf(mo - mn) : 0.0f;
        m = mn;
        s = s*sa + so*sb;
        a0x = a0x*sa + b0x*sb; a0y = a0y*sa + b0y*sb;
        a0z = a0z*sa + b0z*sb; a0w = a0w*sa + b0w*sb;
        a1x = a1x*sa + b1x*sb; a1y = a1y*sa + b1y*sb;
        a1z = a1z*sa + b1z*sb; a1w = a1w*sa + b1w*sb;
        t0 = t0*sa + u0*sb; t1 = t1*sa + u1*sb; t2 = t2*sa + u2*sb;
        t3 = t3*sa + u3*sb; t4 = t4*sa + u4*sb;
    }

    if (g == 0) {
        float inv = 1.0f / s;    // s >= 1 after merge
        float4 s0 = *(const float4*)(g_skip + nb);
        float4 s1 = *(const float4*)(g_skip + nb + 4);
        float hv[8] = {a0x, a0y, a0z, a0w, a1x, a1y, a1z, a1w};
        float tt[5] = {t0, t1, t2, t3, t4};
        #pragma unroll
        for (int d = 0; d < 5; d++) {
            float4 w0 = __ldg((const float4*)(we + d * 64 + li * 8));
            float4 w1 = __ldg((const float4*)(we + d * 64 + li * 8 + 4));
            hv[0] += tt[d]*w0.x; hv[1] += tt[d]*w0.y;
            hv[2] += tt[d]*w0.z; hv[3] += tt[d]*w0.w;
            hv[4] += tt[d]*w1.x; hv[5] += tt[d]*w1.y;
            hv[6] += tt[d]*w1.z; hv[7] += tt[d]*w1.w;
        }
        float4 h0, h1;
        h0.x = hv[0]*inv + s0.x; h0.y = hv[1]*inv + s0.y;
        h0.z = hv[2]*inv + s0.z; h0.w = hv[3]*inv + s0.w;
        h1.x = hv[4]*inv + s1.x; h1.y = hv[5]*inv + s1.y;
        h1.z = hv[6]*inv + s1.z; h1.w = hv[7]*inv + s1.w;
        *(float4*)(g_agg + nb)     = h0;
        *(float4*)(g_agg + nb + 4) = h1;
    }
}

// ---------------- final: out = h @ lin_w + lin_b ---------------------------
__global__ __launch_bounds__(256) void kfinal(const float* __restrict__ lw,
                                              const float* __restrict__ lb,
                                              float* __restrict__ out)
{
    int n = (blockIdx.x * blockDim.x + threadIdx.x) >> 5;
    int lane = threadIdx.x & 31;
    if (n >= NN) return;
    float2 h  = *(const float2*)(g_agg + (size_t)n * 64 + lane * 2);
    float2 wv = *(const float2*)(lw + lane * 2);
    float part = h.x * wv.x + h.y * wv.y;
    #pragma unroll
    for (int o = 16; o; o >>= 1) part += __shfl_xor_sync(0xffffffffu, part, o);
    if (lane == 0) out[n] = part + lb[0];
}

// ---------------- driver ----------------------------------------------------
extern "C" void kernel_launch(void* const* d_in, const int* in_sizes, int n_in,
                              void* d_out, int out_size)
{
    const float* x   = (const float*)d_in[0];
    const int*   ei  = (const int*)d_in[1];       // int32 (jax x64 disabled)
    const float* ea  = (const float*)d_in[2];
    const float* w1q = (const float*)d_in[3];  const float* b1q = (const float*)d_in[4];
    const float* w1k = (const float*)d_in[5];  const float* b1k = (const float*)d_in[6];
    const float* w1v = (const float*)d_in[7];  const float* b1v = (const float*)d_in[8];
    const float* w1e = (const float*)d_in[9];
    const float* w1s = (const float*)d_in[10]; const float* b1s = (const float*)d_in[11];
    const float* wq  = (const float*)d_in[12]; const float* bq  = (const float*)d_in[13];
    const float* wk  = (const float*)d_in[14]; const float* bk  = (const float*)d_in[15];
    const float* wv  = (const float*)d_in[16]; const float* bv  = (const float*)d_in[17];
    const float* we  = (const float*)d_in[18];
    const float* ws  = (const float*)d_in[19]; const float* bs  = (const float*)d_in[20];
    const float* lw  = (const float*)d_in[21]; const float* lb  = (const float*)d_in[22];
    float* out = (float*)d_out;

    cudaFuncSetAttribute(k1_node, cudaFuncAttributeMaxDynamicSharedMemorySize, 88 * 1024);

    const int nb1 = (NN + 63) / 64;
    const size_t smem10 = (size_t)(64 * 10 + 10 * 256 + 256) * sizeof(float);
    const size_t smem64 = (size_t)(64 * 64 + 64 * 256 + 256) * sizeof(float);
    const int nbN = (NN + 255) / 256;
    const int nbE = (NE + 255) / 256;
    const int nbW = (NN * 32 + 255) / 256;   // warp-per-node grids

    // build CSR (edge_index constant; rebuilt identically each replay)
    kzero<<<nbN, 256>>>();
    khist<<<nbE, 256>>>(ei);
    kscan<<<1, 1024>>>();
    kscatter<<<nbE, 256>>>(ei, ea);

    // layer 0 (10 -> 64)
    k1_node<<<nb1, 256, smem10>>>(x, 10, 0, w1q, b1q, w1k, b1k, w1v, b1v, w1s, b1s);
    kedge<<<nbW, 256>>>(w1e);

    // layers 1..5 (64 -> 64)
    for (int l = 0; l < 5; l++) {
        k1_node<<<nb1, 256, smem64>>>(nullptr, 64, 1,
                                      wq + l * 4096, bq + l * 64,
                                      wk + l * 4096, bk + l * 64,
                                      wv + l * 4096, bv + l * 64,
                                      ws + l * 4096, bs + l * 64);
        kedge<<<nbW, 256>>>(we + l * 320);
    }

    kfinal<<<nbW, 256>>>(lw, lb, out);
}

// round 14
// speedup vs baseline: 1.1847x; 1.0442x over previous
#include <cuda_runtime.h>
#include <cstdint>

#define NN 50000
#define NE 800000
#define HID 64
#define NB_SCAN ((NN + 255) / 256)   // 196 blocks of 256

// ---------------- scratch (device globals; no allocations allowed) ----------
__device__ __align__(16) float g_q[NN * HID];
__device__ __align__(16) float g_k[NN * HID];
__device__ __align__(16) float g_v[NN * HID];
__device__ __align__(16) float g_skip[NN * HID];
__device__ __align__(16) float g_agg[NN * HID];     // h between layers
__device__ __align__(16) float g_eLs[NE * 5];       // log1p(edge_attr), sorted by dst
__device__ __align__(16) int   g_srcs[NE];          // src node, sorted by dst
__device__ __align__(16) int   g_rowptr[NN + 1];
__device__ __align__(16) int   g_cnt[NN];
__device__ __align__(16) int   g_bsum[NB_SCAN];

#define NEG_INF __int_as_float(0xff800000)

__device__ __forceinline__ unsigned long long pack2(float lo, float hi) {
    unsigned long long r;
    asm("mov.b64 %0, {%1, %2};" : "=l"(r) : "f"(lo), "f"(hi));
    return r;
}
__device__ __forceinline__ void ffma2(unsigned long long& d,
                                      unsigned long long a, unsigned long long b) {
    asm("fma.rn.f32x2 %0, %1, %2, %0;" : "+l"(d) : "l"(a), "l"(b));
}

// ---------------- CSR build: zero, histogram, 3-stage scan, scatter --------
__global__ void kzero() {
    int i = blockIdx.x * blockDim.x + threadIdx.x;
    if (i < NN) g_cnt[i] = 0;
}

__global__ void khist(const int* __restrict__ ei) {
    int e = blockIdx.x * blockDim.x + threadIdx.x;
    if (e < NE) atomicAdd(&g_cnt[ei[NE + e]], 1);
}

// stage 1: per-block sums of g_cnt -> g_bsum
__global__ __launch_bounds__(256) void kscan1() {
    __shared__ int wsum[8];
    int t = threadIdx.x, b = blockIdx.x;
    int i = b * 256 + t;
    int v = (i < NN) ? g_cnt[i] : 0;
    int lane = t & 31, w = t >> 5;
    #pragma unroll
    for (int o = 16; o; o >>= 1) v += __shfl_xor_sync(0xffffffffu, v, o);
    if (lane == 0) wsum[w] = v;
    __syncthreads();
    if (t == 0) {
        int s = 0;
        #pragma unroll
        for (int j = 0; j < 8; j++) s += wsum[j];
        g_bsum[b] = s;
    }
}

// stage 2: one block scans the 196 block sums (exclusive); sets rowptr[NN]
__global__ __launch_bounds__(256) void kscan2() {
    __shared__ int wsum[8];
    int t = threadIdx.x;
    int lane = t & 31, w = t >> 5;
    int v = (t < NB_SCAN) ? g_bsum[t] : 0;
    int x = v;
    #pragma unroll
    for (int o = 1; o < 32; o <<= 1) {
        int y = __shfl_up_sync(0xffffffffu, x, o);
        if (lane >= o) x += y;
    }
    if (lane == 31) wsum[w] = x;
    __syncthreads();
    if (w == 0) {
        int ws = (lane < 8) ? wsum[lane] : 0;
        #pragma unroll
        for (int o = 1; o < 8; o <<= 1) {
            int y = __shfl_up_sync(0xffffffffu, ws, o);
            if (lane >= o) ws += y;
        }
        if (lane < 8) wsum[lane] = ws;
    }
    __syncthreads();
    int incl = x + (w > 0 ? wsum[w - 1] : 0);
    if (t < NB_SCAN) g_bsum[t] = incl - v;     // exclusive
    if (t == 255) g_rowptr[NN] = incl;          // total (v=0 past NB_SCAN)
}

// stage 3: local exclusive scan + block offset -> g_rowptr; re-zero g_cnt
__global__ __launch_bounds__(256) void kscan3() {
    __shared__ int wsum[8];
    int t = threadIdx.x, b = blockIdx.x;
    int i = b * 256 + t;
    int v = (i < NN) ? g_cnt[i] : 0;
    if (i < NN) g_cnt[i] = 0;
    int lane = t & 31, w = t >> 5;
    int x = v;
    #pragma unroll
    for (int o = 1; o < 32; o <<= 1) {
        int y = __shfl_up_sync(0xffffffffu, x, o);
        if (lane >= o) x += y;
    }
    if (lane == 31) wsum[w] = x;
    __syncthreads();
    if (w == 0) {
        int ws = (lane < 8) ? wsum[lane] : 0;
        #pragma unroll
        for (int o = 1; o < 8; o <<= 1) {
            int y = __shfl_up_sync(0xffffffffu, ws, o);
            if (lane >= o) ws += y;
        }
        if (lane < 8) wsum[lane] = ws;
    }
    __syncthreads();
    int excl = x - v + (w > 0 ? wsum[w - 1] : 0) + g_bsum[b];
    if (i < NN) g_rowptr[i] = excl;
}

__global__ void kscatter(const int* __restrict__ ei, const float* __restrict__ ea) {
    int e = blockIdx.x * blockDim.x + threadIdx.x;
    if (e >= NE) return;
    int sn = ei[e], dn = ei[NE + e];
    int pos = g_rowptr[dn] + atomicAdd(&g_cnt[dn], 1);
    g_srcs[pos] = sn;
    #pragma unroll
    for (int d = 0; d < 5; d++)
        g_eLs[pos * 5 + d] = log1pf(ea[e * 5 + d]);
}

// ---------------- K1: per-layer node GEMM (q,k,v,skip fused, f32x2) --------
__global__ __launch_bounds__(256) void k1_node(
    const float* __restrict__ xin, int kin, int mode,
    const float* __restrict__ wq, const float* __restrict__ bq,
    const float* __restrict__ wk, const float* __restrict__ bk,
    const float* __restrict__ wv, const float* __restrict__ bv,
    const float* __restrict__ wsk, const float* __restrict__ bsk)
{
    extern __shared__ float smbuf[];
    float* hs = smbuf;                        // [kin][64]  (hs[c*64+r])
    float* Ws = smbuf + 64 * kin;             // [kin][256]
    float* Bs = Ws + kin * 256;               // [256]

    const int t = threadIdx.x;
    const int base = blockIdx.x * 64;

    {
        const float* wptr[4] = {wq, wk, wv, wsk};
        for (int idx = t; idx < kin * 256; idx += 256) {
            int kk = idx >> 8, cc = idx & 255;
            Ws[idx] = wptr[cc >> 6][kk * 64 + (cc & 63)];
        }
        const float* bptr[4] = {bq, bk, bv, bsk};
        Bs[t] = bptr[t >> 6][t & 63];
    }

    if (mode == 0) {
        for (int idx = t; idx < 64 * kin; idx += 256) {
            int r = idx / kin, c = idx - r * kin;
            int n = base + r;
            hs[c * 64 + r] = (n < NN) ? log1pf(xin[n * 10 + c]) : 0.0f;
        }
    } else {
        int r = t >> 2;
        int n = base + r;
        #pragma unroll
        for (int i = 0; i < 4; i++) {
            int q = (t & 3) + 4 * i;            // 0..15
            float4 va = (n < NN)
                ? *(const float4*)(g_agg + (size_t)n * 64 + q * 4)
                : make_float4(0.f, 0.f, 0.f, 0.f);
            hs[(q * 4 + 0) * 64 + r] = va.x;
            hs[(q * 4 + 1) * 64 + r] = va.y;
            hs[(q * 4 + 2) * 64 + r] = va.z;
            hs[(q * 4 + 3) * 64 + r] = va.w;
        }
    }
    __syncthreads();

    const int tc = t & 31;   // col pairs: 2*tc + 64*jj
    const int tr = t >> 5;   // nodes: tr*8 + i

    unsigned long long acc[8][4];
    #pragma unroll
    for (int jj = 0; jj < 4; jj++) {
        float2 b2 = *(const float2*)(Bs + jj * 64 + 2 * tc);
        unsigned long long bb = pack2(b2.x, b2.y);
        #pragma unroll
        for (int i = 0; i < 8; i++) acc[i][jj] = bb;
    }

    for (int kk = 0; kk < kin; kk++) {
        float4 ha = *(const float4*)(hs + kk * 64 + tr * 8);      // broadcast
        float4 hb = *(const float4*)(hs + kk * 64 + tr * 8 + 4);  // broadcast
        unsigned long long hv[8];
        hv[0] = pack2(ha.x, ha.x); hv[1] = pack2(ha.y, ha.y);
        hv[2] = pack2(ha.z, ha.z); hv[3] = pack2(ha.w, ha.w);
        hv[4] = pack2(hb.x, hb.x); hv[5] = pack2(hb.y, hb.y);
        hv[6] = pack2(hb.z, hb.z); hv[7] = pack2(hb.w, hb.w);
        unsigned long long wv2[4];
        #pragma unroll
        for (int jj = 0; jj < 4; jj++)
            wv2[jj] = *(const unsigned long long*)(Ws + kk * 256 + jj * 64 + 2 * tc);
        #pragma unroll
        for (int i = 0; i < 8; i++)
            #pragma unroll
            for (int jj = 0; jj < 4; jj++)
                ffma2(acc[i][jj], hv[i], wv2[jj]);
    }

    float* mats[4] = {g_q, g_k, g_v, g_skip};
    #pragma unroll
    for (int i = 0; i < 8; i++) {
        int n = base + tr * 8 + i;
        if (n >= NN) continue;
        #pragma unroll
        for (int jj = 0; jj < 4; jj++)
            *(unsigned long long*)(mats[jj] + (size_t)n * 64 + 2 * tc) = acc[i][jj];
    }
}

// ---------------- kedge: warp-per-node, 4 edges in flight, branchless, -----
// with software prefetch of the next src index to break the
// srcs->gather serial load chain.
__global__ __launch_bounds__(256) void kedge(const float* __restrict__ we)
{
    int n = (blockIdx.x * 256 + threadIdx.x) >> 5;
    int lane = threadIdx.x & 31;
    int g  = lane >> 3;
    int li = lane & 7;
    unsigned gmask = 0xFFu << (g * 8);
    if (n >= NN) return;

    const int start = g_rowptr[n];
    const int end   = g_rowptr[n + 1];
    const size_t nb = (size_t)n * 64 + li * 8;

    if (start == end) {                 // degree 0: h = skip
        if (g == 0) {
            float4 s0 = *(const float4*)(g_skip + nb);
            float4 s1 = *(const float4*)(g_skip + nb + 4);
            *(float4*)(g_agg + nb)     = s0;
            *(float4*)(g_agg + nb + 4) = s1;
        }
        return;
    }

    float4 q0 = *(const float4*)(g_q + nb);
    float4 q1 = *(const float4*)(g_q + nb + 4);

    // r[d] = we[d,:] . q   (group-local reduction; all groups same value)
    float r[5];
    #pragma unroll
    for (int d = 0; d < 5; d++) {
        float4 w0 = __ldg((const float4*)(we + d * 64 + li * 8));
        float4 w1 = __ldg((const float4*)(we + d * 64 + li * 8 + 4));
        float pr = w0.x*q0.x + w0.y*q0.y + w0.z*q0.z + w0.w*q0.w
                 + w1.x*q1.x + w1.y*q1.y + w1.z*q1.z + w1.w*q1.w;
        pr += __shfl_xor_sync(gmask, pr, 1);
        pr += __shfl_xor_sync(gmask, pr, 2);
        pr += __shfl_xor_sync(gmask, pr, 4);
        r[d] = pr;
    }

    float m = NEG_INF, s = 0.0f;
    float a0x=0, a0y=0, a0z=0, a0w=0, a1x=0, a1y=0, a1z=0, a1w=0;
    float t0=0, t1=0, t2=0, t3=0, t4=0;

    // prefetch first src index (clamped: end-1 >= start is valid here)
    int sn = __ldg(g_srcs + min(start + g, end - 1));

    for (int p0 = start + g; p0 < end; p0 += 4) {
        // prefetch next iteration's src index NOW (overlaps current gather)
        int sn_next = __ldg(g_srcs + min(p0 + 4, end - 1));

        const float* kp = g_k + (size_t)sn * 64 + li * 8;
        const float* vp = g_v + (size_t)sn * 64 + li * 8;
        float4 k0 = *(const float4*)(kp);
        float4 k1 = *(const float4*)(kp + 4);
        float4 v0 = *(const float4*)(vp);
        float4 v1 = *(const float4*)(vp + 4);
        float e0 = __ldg(g_eLs + p0 * 5 + 0), e1 = __ldg(g_eLs + p0 * 5 + 1),
              e2 = __ldg(g_eLs + p0 * 5 + 2), e3 = __ldg(g_eLs + p0 * 5 + 3),
              e4 = __ldg(g_eLs + p0 * 5 + 4);

        float dot = q0.x*k0.x + q0.y*k0.y + q0.z*k0.z + q0.w*k0.w
                  + q1.x*k1.x + q1.y*k1.y + q1.z*k1.z + q1.w*k1.w;
        dot += __shfl_xor_sync(gmask, dot, 1);
        dot += __shfl_xor_sync(gmask, dot, 2);
        dot += __shfl_xor_sync(gmask, dot, 4);
        float lg = (dot + r[0]*e0 + r[1]*e1 + r[2]*e2 + r[3]*e3 + r[4]*e4) * 0.125f;

        // branchless online rescale: first iter sc = exp(-inf) = 0
        float mn = fmaxf(m, lg);
        float sc = __expf(m - mn);
        float p  = __expf(lg - mn);
        m = mn;
        s   = s  *sc + p;
        a0x = a0x*sc + p*v0.x; a0y = a0y*sc + p*v0.y;
        a0z = a0z*sc + p*v0.z; a0w = a0w*sc + p*v0.w;
        a1x = a1x*sc + p*v1.x; a1y = a1y*sc + p*v1.y;
        a1z = a1z*sc + p*v1.z; a1w = a1w*sc + p*v1.w;
        t0  = t0 *sc + p*e0;   t1  = t1 *sc + p*e1;
        t2  = t2 *sc + p*e2;   t3  = t3 *sc + p*e3;
        t4  = t4 *sc + p*e4;

        sn = sn_next;
    }

    // merge the 4 group states (lanes at xor 8, 16 hold the same dims)
    #pragma unroll
    for (int off = 8; off <= 16; off <<= 1) {
        float mo  = __shfl_xor_sync(0xffffffffu, m,  off);
        float so  = __shfl_xor_sync(0xffffffffu, s,  off);
        float b0x = __shfl_xor_sync(0xffffffffu, a0x, off);
        float b0y = __shfl_xor_sync(0xffffffffu, a0y, off);
        float b0z = __shfl_xor_sync(0xffffffffu, a0z, off);
        float b0w = __shfl_xor_sync(0xffffffffu, a0w, off);
        float b1x = __shfl_xor_sync(0xffffffffu, a1x, off);
        float b1y = __shfl_xor_sync(0xffffffffu, a1y, off);
        float b1z = __shfl_xor_sync(0xffffffffu, a1z, off);
        float b1w = __shfl_xor_sync(0xffffffffu, a1w, off);
        float u0  = __shfl_xor_sync(0xffffffffu, t0, off);
        float u1  = __shfl_xor_sync(0xffffffffu, t1, off);
        float u2  = __shfl_xor_sync(0xffffffffu, t2, off);
        float u3  = __shfl_xor_sync(0xffffffffu, t3, off);
        float u4  = __shfl_xor_sync(0xffffffffu, t4, off);

        float mn = fmaxf(m, mo);
        float sa = (m  > NEG_INF) ? __expf(m  - mn) : 0.0f;  // guard empty groups
        float sb = (mo > NEG_INF) ? __expf(mo - mn) : 0.0f;
        m = mn;
        s = s*sa + so*sb;
        a0x = a0x*sa + b0x*sb; a0y = a0y*sa + b0y*sb;
        a0z = a0z*sa + b0z*sb; a0w = a0w*sa + b0w*sb;
        a1x = a1x*sa + b1x*sb; a1y = a1y*sa + b1y*sb;
        a1z = a1z*sa + b1z*sb; a1w = a1w*sa + b1w*sb;
        t0 = t0*sa + u0*sb; t1 = t1*sa + u1*sb; t2 = t2*sa + u2*sb;
        t3 = t3*sa + u3*sb; t4 = t4*sa + u4*sb;
    }

    if (g == 0) {
        float inv = 1.0f / s;    // s >= 1 after merge
        float4 s0 = *(const float4*)(g_skip + nb);
        float4 s1 = *(const float4*)(g_skip + nb + 4);
        float hv[8] = {a0x, a0y, a0z, a0w, a1x, a1y, a1z, a1w};
        float tt[5] = {t0, t1, t2, t3, t4};
        #pragma unroll
        for (int d = 0; d < 5; d++) {
            float4 w0 = __ldg((const float4*)(we + d * 64 + li * 8));
            float4 w1 = __ldg((const float4*)(we + d * 64 + li * 8 + 4));
            hv[0] += tt[d]*w0.x; hv[1] += tt[d]*w0.y;
            hv[2] += tt[d]*w0.z; hv[3] += tt[d]*w0.w;
            hv[4] += tt[d]*w1.x; hv[5] += tt[d]*w1.y;
            hv[6] += tt[d]*w1.z; hv[7] += tt[d]*w1.w;
        }
        float4 h0, h1;
        h0.x = hv[0]*inv + s0.x; h0.y = hv[1]*inv + s0.y;
        h0.z = hv[2]*inv + s0.z; h0.w = hv[3]*inv + s0.w;
        h1.x = hv[4]*inv + s1.x; h1.y = hv[5]*inv + s1.y;
        h1.z = hv[6]*inv + s1.z; h1.w = hv[7]*inv + s1.w;
        *(float4*)(g_agg + nb)     = h0;
        *(float4*)(g_agg + nb + 4) = h1;
    }
}

// ---------------- final: out = h @ lin_w + lin_b ---------------------------
__global__ __launch_bounds__(256) void kfinal(const float* __restrict__ lw,
                                              const float* __restrict__ lb,
                                              float* __restrict__ out)
{
    int n = (blockIdx.x * blockDim.x + threadIdx.x) >> 5;
    int lane = threadIdx.x & 31;
    if (n >= NN) return;
    float2 h  = *(const float2*)(g_agg + (size_t)n * 64 + lane * 2);
    float2 wv = *(const float2*)(lw + lane * 2);
    float part = h.x * wv.x + h.y * wv.y;
    #pragma unroll
    for (int o = 16; o; o >>= 1) part += __shfl_xor_sync(0xffffffffu, part, o);
    if (lane == 0) out[n] = part + lb[0];
}

// ---------------- driver ----------------------------------------------------
extern "C" void kernel_launch(void* const* d_in, const int* in_sizes, int n_in,
                              void* d_out, int out_size)
{
    const float* x   = (const float*)d_in[0];
    const int*   ei  = (const int*)d_in[1];       // int32 (jax x64 disabled)
    const float* ea  = (const float*)d_in[2];
    const float* w1q = (const float*)d_in[3];  const float* b1q = (const float*)d_in[4];
    const float* w1k = (const float*)d_in[5];  const float* b1k = (const float*)d_in[6];
    const float* w1v = (const float*)d_in[7];  const float* b1v = (const float*)d_in[8];
    const float* w1e = (const float*)d_in[9];
    const float* w1s = (const float*)d_in[10]; const float* b1s = (const float*)d_in[11];
    const float* wq  = (const float*)d_in[12]; const float* bq  = (const float*)d_in[13];
    const float* wk  = (const float*)d_in[14]; const float* bk  = (const float*)d_in[15];
    const float* wv  = (const float*)d_in[16]; const float* bv  = (const float*)d_in[17];
    const float* we  = (const float*)d_in[18];
    const float* ws  = (const float*)d_in[19]; const float* bs  = (const float*)d_in[20];
    const float* lw  = (const float*)d_in[21]; const float* lb  = (const float*)d_in[22];
    float* out = (float*)d_out;

    cudaFuncSetAttribute(k1_node, cudaFuncAttributeMaxDynamicSharedMemorySize, 88 * 1024);

    const int nb1 = (NN + 63) / 64;
    const size_t smem10 = (size_t)(64 * 10 + 10 * 256 + 256) * sizeof(float);
    const size_t smem64 = (size_t)(64 * 64 + 64 * 256 + 256) * sizeof(float);
    const int nbE = (NE + 255) / 256;
    const int nbW = (NN * 32 + 255) / 256;   // warp-per-node grids

    // build CSR (edge_index constant; rebuilt identically each replay)
    kzero<<<NB_SCAN, 256>>>();
    khist<<<nbE, 256>>>(ei);
    kscan1<<<NB_SCAN, 256>>>();
    kscan2<<<1, 256>>>();
    kscan3<<<NB_SCAN, 256>>>();
    kscatter<<<nbE, 256>>>(ei, ea);

    // layer 0 (10 -> 64)
    k1_node<<<nb1, 256, smem10>>>(x, 10, 0, w1q, b1q, w1k, b1k, w1v, b1v, w1s, b1s);
    kedge<<<nbW, 256>>>(w1e);

    // layers 1..5 (64 -> 64)
    for (int l = 0; l < 5; l++) {
        k1_node<<<nb1, 256, smem64>>>(nullptr, 64, 1,
                                      wq + l * 4096, bq + l * 64,
                                      wk + l * 4096, bk + l * 64,
                                      wv + l * 4096, bv + l * 64,
                                      ws + l * 4096, bs + l * 64);
        kedge<<<nbW, 256>>>(we + l * 320);
    }

    kfinal<<<nbW, 256>>>(lw, lb, out);
}